// round 7
// baseline (speedup 1.0000x reference)
#include <cuda_runtime.h>

#define N_NODES 50000
#define N_EDGES 1000000
#define D_IN    64
#define D_HID   64
#define D_OUTF  32

// ---- scratch (no allocs). Device globals referenced ONLY in device code. ----
__device__ float  g_deg [N_NODES];
__device__ float  g_dinv[N_NODES];
__device__ int    g_cnt [N_NODES];
__device__ int    g_rowstart[N_NODES + 1];
__device__ int    g_cursor[N_NODES];
__device__ float2 g_adj [N_EDGES];             // (src bits, w), dst-grouped
__device__ float  g_h   [N_NODES * D_HID];     // hs (pre-scaled by dinv)
__device__ float  g_agg [N_NODES * D_HID];     // layer-1 output

// ---------------- CSR build ----------------
__global__ void k_zero() {
    int i = blockIdx.x * blockDim.x + threadIdx.x;
    if (i < N_NODES) { g_cnt[i] = 0; g_deg[i] = 0.0f; }
}

// 4 edges per thread: independent atomics in flight.
__global__ void k_hist(const int* __restrict__ dst, const float* __restrict__ w) {
    int t = blockIdx.x * blockDim.x + threadIdx.x;
    int e0 = t * 4;
#pragma unroll
    for (int j = 0; j < 4; j++) {
        int e = e0 + j;
        if (e < N_EDGES) {
            atomicAdd(&g_cnt[dst[e]], 1);
            atomicAdd(&g_deg[dst[e]], w[e]);
        }
    }
}

// single-block (512 threads) exclusive scan of g_cnt; also dinv.
// unroll 4: batched loads (MLP) without a spill-scale live range.
__global__ __launch_bounds__(512) void k_scan() {
    constexpr int NT  = 512;
    constexpr int PER = (N_NODES + NT - 1) / NT;   // 98
    __shared__ int bs[NT];
    int t = threadIdx.x;
    int base = t * PER;

    int s = 0;
#pragma unroll 4
    for (int i = 0; i < PER; i++) {
        int idx = base + i;
        if (idx < N_NODES) s += g_cnt[idx];
    }
    bs[t] = s;
    __syncthreads();
#pragma unroll 1
    for (int off = 1; off < NT; off <<= 1) {
        int v = (t >= off) ? bs[t - off] : 0;
        __syncthreads();
        bs[t] += v;
        __syncthreads();
    }
    int run = bs[t] - s;

#pragma unroll 4
    for (int i = 0; i < PER; i++) {
        int idx = base + i;
        if (idx < N_NODES) {
            g_rowstart[idx] = run;
            g_cursor[idx]   = run;
            run += g_cnt[idx];
            g_dinv[idx] = rsqrtf(1.0f + g_deg[idx]);   // + self-loop
            if (idx == N_NODES - 1) g_rowstart[N_NODES] = run;
        }
    }
}

// 4 edges per thread: overlap the 318-cyc atomic-return latencies.
__global__ void k_permute(const int* __restrict__ src, const int* __restrict__ dst,
                          const float* __restrict__ w) {
    int t = blockIdx.x * blockDim.x + threadIdx.x;
    int e0 = t * 4;
#pragma unroll
    for (int j = 0; j < 4; j++) {
        int e = e0 + j;
        if (e < N_EDGES) {
            int p = atomicAdd(&g_cursor[dst[e]], 1);
            g_adj[p] = make_float2(__int_as_float(src[e]), w[e]);
        }
    }
}

// ---------------- register-blocked GEMM + dinv scale ----------------
template <int DO, int LAYER>
__global__ __launch_bounds__(256) void k_gemm_scale(
        const float* __restrict__ Xparam, const float* __restrict__ W) {
    constexpr int DI   = 64;
    constexpr int TX   = DO / 4;
    constexpr int TYN  = 256 / TX;
    constexpr int ROWS = TYN * 4;
    constexpr int XS   = ROWS + 4;

    __shared__ float Ws[DI * DO];
    __shared__ float xsT[DI * XS];

    const float* X = (LAYER == 1) ? Xparam : g_agg;

    const int tid = threadIdx.x;
    const int tx  = tid % TX;
    const int ty  = tid / TX;
    const int blockRow = blockIdx.x * ROWS;

    for (int i = tid; i < DI * DO / 4; i += 256)
        reinterpret_cast<float4*>(Ws)[i] = reinterpret_cast<const float4*>(W)[i];

    for (int i = tid; i < ROWS * (DI / 4); i += 256) {
        int row = i / (DI / 4);
        int c4  = i % (DI / 4);
        int gr  = blockRow + row;
        float4 v = make_float4(0.f, 0.f, 0.f, 0.f);
        if (gr < N_NODES)
            v = reinterpret_cast<const float4*>(X + gr * DI)[c4];
        xsT[(c4 * 4 + 0) * XS + row] = v.x;
        xsT[(c4 * 4 + 1) * XS + row] = v.y;
        xsT[(c4 * 4 + 2) * XS + row] = v.z;
        xsT[(c4 * 4 + 3) * XS + row] = v.w;
    }
    __syncthreads();

    float acc[4][4];
#pragma unroll
    for (int i = 0; i < 4; i++)
#pragma unroll
        for (int j = 0; j < 4; j++) acc[i][j] = 0.0f;

#pragma unroll
    for (int k = 0; k < DI; k++) {
        float4 a = *reinterpret_cast<const float4*>(&xsT[k * XS + ty * 4]);
        float4 b = *reinterpret_cast<const float4*>(&Ws [k * DO + tx * 4]);
        acc[0][0] += a.x * b.x; acc[0][1] += a.x * b.y; acc[0][2] += a.x * b.z; acc[0][3] += a.x * b.w;
        acc[1][0] += a.y * b.x; acc[1][1] += a.y * b.y; acc[1][2] += a.y * b.z; acc[1][3] += a.y * b.w;
        acc[2][0] += a.z * b.x; acc[2][1] += a.z * b.y; acc[2][2] += a.z * b.z; acc[2][3] += a.z * b.w;
        acc[3][0] += a.w * b.x; acc[3][1] += a.w * b.y; acc[3][2] += a.w * b.z; acc[3][3] += a.w * b.w;
    }

#pragma unroll
    for (int i = 0; i < 4; i++) {
        int row = blockRow + ty * 4 + i;
        if (row >= N_NODES) break;
        float dv = g_dinv[row];
        float4 v = make_float4(dv * acc[i][0], dv * acc[i][1],
                               dv * acc[i][2], dv * acc[i][3]);
        *reinterpret_cast<float4*>(&g_h[row * DO + tx * 4]) = v;
    }
}

// ---------------- pull-gather, no shfl, unroll-8 load batching ----------------
// One warp per node. Per edge: broadcast __ldg of g_adj[i] (L1-hit; address affine
// in i, independent across iterations) + one coalesced h-row gather. unroll 8 lets
// ptxas front-batch 8 adj loads then 8 row loads -> MLP ~8 per warp.

// LAYER 1, D=64: lane owns float2; writes g_agg.
__global__ __launch_bounds__(256) void k_gather64(const float* __restrict__ b) {
    int node = (blockIdx.x * blockDim.x + threadIdx.x) >> 5;
    int lane = threadIdx.x & 31;
    if (node >= N_NODES) return;

    int beg = g_rowstart[node];
    int end = g_rowstart[node + 1];

    float2 acc = *reinterpret_cast<const float2*>(&g_h[node * 64 + lane * 2]);  // self-loop
#pragma unroll 8
    for (int i = beg; i < end; i++) {
        float2 ev = __ldg(&g_adj[i]);
        int   s   = __float_as_int(ev.x);
        float2 hv = *reinterpret_cast<const float2*>(&g_h[s * 64 + lane * 2]);
        acc.x += ev.y * hv.x;
        acc.y += ev.y * hv.y;
    }
    float dv = g_dinv[node];
    float2 bb = *reinterpret_cast<const float2*>(&b[lane * 2]);
    float2 r  = make_float2(fmaxf(dv * acc.x + bb.x, 0.0f),
                            fmaxf(dv * acc.y + bb.y, 0.0f));
    *reinterpret_cast<float2*>(&g_agg[node * 64 + lane * 2]) = r;
}

// LAYER 2, D=32: lane owns one column; writes d_out.
__global__ __launch_bounds__(256) void k_gather32(const float* __restrict__ b,
                                                  float* __restrict__ OUT) {
    int node = (blockIdx.x * blockDim.x + threadIdx.x) >> 5;
    int lane = threadIdx.x & 31;
    if (node >= N_NODES) return;

    int beg = g_rowstart[node];
    int end = g_rowstart[node + 1];

    float acc = g_h[node * 32 + lane];   // self-loop
#pragma unroll 8
    for (int i = beg; i < end; i++) {
        float2 ev = __ldg(&g_adj[i]);
        int   s   = __float_as_int(ev.x);
        acc += ev.y * g_h[s * 32 + lane];
    }
    float dv = g_dinv[node];
    OUT[node * 32 + lane] = fmaxf(dv * acc + b[lane], 0.0f);
}

extern "C" void kernel_launch(void* const* d_in, const int* in_sizes, int n_in,
                              void* d_out, int out_size) {
    const float* x   = (const float*)d_in[0];
    const int*   ei  = (const int*)  d_in[1];   // [2, E]
    const float* ew  = (const float*)d_in[2];
    const float* W1  = (const float*)d_in[3];
    const float* b1  = (const float*)d_in[4];
    const float* W2  = (const float*)d_in[5];
    const float* b2  = (const float*)d_in[6];
    float*       out = (float*)d_out;

    const int* src = ei;
    const int* dst = ei + N_EDGES;

    // CSR build + norm
    k_zero   <<<(N_NODES + 255) / 256, 256>>>();
    k_hist   <<<(N_EDGES / 4 + 255) / 256, 256>>>(dst, ew);
    k_scan   <<<1, 512>>>();
    k_permute<<<(N_EDGES / 4 + 255) / 256, 256>>>(src, dst, ew);

    // ---- layer 1 ----
    k_gemm_scale<D_HID, 1><<<(N_NODES + 63) / 64, 256>>>(x, W1);
    k_gather64<<<(N_NODES * 32 + 255) / 256, 256>>>(b1);

    // ---- layer 2 ----
    k_gemm_scale<D_OUTF, 2><<<(N_NODES + 127) / 128, 256>>>(nullptr, W2);
    k_gather32<<<(N_NODES * 32 + 255) / 256, 256>>>(b2, out);
}

// round 8
// speedup vs baseline: 1.8473x; 1.8473x over previous
#include <cuda_runtime.h>

#define N_NODES 50000
#define N_EDGES 1000000
#define D_IN    64
#define D_HID   64
#define D_OUTF  32

// ---- scratch (no allocs). Device globals referenced ONLY in device code. ----
__device__ float g_deg [N_NODES];
__device__ float g_h   [N_NODES * D_HID];   // hs = dinv*(X@W)
__device__ float g_agg [N_NODES * D_HID];   // layer-1 aggregation -> out1 in place

__device__ __forceinline__ void red_add_v4(float* p, float4 v) {
    asm volatile("red.global.add.v4.f32 [%0], {%1, %2, %3, %4};"
                 :: "l"(p), "f"(v.x), "f"(v.y), "f"(v.z), "f"(v.w) : "memory");
}

// ---------------- degree ----------------
__global__ void k_deg_init() {
    int i = blockIdx.x * blockDim.x + threadIdx.x;
    if (i < N_NODES) g_deg[i] = 1.0f;          // self-loop weight
}

// 4 edges per thread: independent atomics in flight.
__global__ void k_deg_count(const int* __restrict__ dst, const float* __restrict__ w) {
    int t = blockIdx.x * blockDim.x + threadIdx.x;
    int e0 = t * 4;
#pragma unroll
    for (int j = 0; j < 4; j++) {
        int e = e0 + j;
        if (e < N_EDGES) atomicAdd(&g_deg[dst[e]], w[e]);
    }
}

// ---------------- GEMM DO=64: 4 rows x 8 cols per thread ----------------
// 128 threads/block, 64-row tile. 3x LDS.128 feed 32 FFMA.
// Epilogue: v = rsqrt(deg[row]) * acc; writes g_h and g_agg (self-loop init).
template <int LAYER>
__global__ __launch_bounds__(128) void k_gemm64(
        const float* __restrict__ Xparam, const float* __restrict__ W) {
    constexpr int DI = 64, DO = 64;
    constexpr int TX = 8;                 // col groups of 8
    constexpr int ROWS = 64;              // (128/TX)*4
    constexpr int XS = ROWS + 4;

    __shared__ float Ws [DI * DO];        // 16 KB
    __shared__ float xsT[DI * XS];        // 17.4 KB

    const float* X = (LAYER == 1) ? Xparam : g_agg;

    const int tid = threadIdx.x;
    const int tx  = tid % TX;             // cols tx*8 .. +7
    const int ty  = tid / TX;             // rows ty*4 .. +3
    const int blockRow = blockIdx.x * ROWS;

    for (int i = tid; i < DI * DO / 4; i += 128)
        reinterpret_cast<float4*>(Ws)[i] = reinterpret_cast<const float4*>(W)[i];

    for (int i = tid; i < ROWS * (DI / 4); i += 128) {
        int row = i / (DI / 4);
        int c4  = i % (DI / 4);
        int gr  = blockRow + row;
        float4 v = make_float4(0.f, 0.f, 0.f, 0.f);
        if (gr < N_NODES)
            v = reinterpret_cast<const float4*>(X + gr * DI)[c4];
        xsT[(c4 * 4 + 0) * XS + row] = v.x;
        xsT[(c4 * 4 + 1) * XS + row] = v.y;
        xsT[(c4 * 4 + 2) * XS + row] = v.z;
        xsT[(c4 * 4 + 3) * XS + row] = v.w;
    }
    __syncthreads();

    float acc[4][8];
#pragma unroll
    for (int i = 0; i < 4; i++)
#pragma unroll
        for (int j = 0; j < 8; j++) acc[i][j] = 0.0f;

#pragma unroll
    for (int k = 0; k < DI; k++) {
        float4 a  = *reinterpret_cast<const float4*>(&xsT[k * XS + ty * 4]);
        float4 b0 = *reinterpret_cast<const float4*>(&Ws [k * DO + tx * 8]);
        float4 b1 = *reinterpret_cast<const float4*>(&Ws [k * DO + tx * 8 + 4]);
        float av[4] = {a.x, a.y, a.z, a.w};
        float bv[8] = {b0.x, b0.y, b0.z, b0.w, b1.x, b1.y, b1.z, b1.w};
#pragma unroll
        for (int i = 0; i < 4; i++)
#pragma unroll
            for (int j = 0; j < 8; j++)
                acc[i][j] += av[i] * bv[j];
    }

#pragma unroll
    for (int i = 0; i < 4; i++) {
        int row = blockRow + ty * 4 + i;
        if (row >= N_NODES) break;
        float dv = rsqrtf(g_deg[row]);
        float4 v0 = make_float4(dv * acc[i][0], dv * acc[i][1], dv * acc[i][2], dv * acc[i][3]);
        float4 v1 = make_float4(dv * acc[i][4], dv * acc[i][5], dv * acc[i][6], dv * acc[i][7]);
        *reinterpret_cast<float4*>(&g_h  [row * DO + tx * 8])     = v0;
        *reinterpret_cast<float4*>(&g_h  [row * DO + tx * 8 + 4]) = v1;
        *reinterpret_cast<float4*>(&g_agg[row * DO + tx * 8])     = v0;
        *reinterpret_cast<float4*>(&g_agg[row * DO + tx * 8 + 4]) = v1;
    }
}

// ---------------- GEMM DO=32: 4x4 per thread (R2 config), X = g_agg ----------------
__global__ __launch_bounds__(256) void k_gemm32(const float* __restrict__ W,
                                                float* __restrict__ OUT) {
    constexpr int DI = 64, DO = 32;
    constexpr int TX = 8, ROWS = 128, XS = ROWS + 4;

    __shared__ float Ws [DI * DO];        // 8 KB
    __shared__ float xsT[DI * XS];        // 33.8 KB

    const int tid = threadIdx.x;
    const int tx  = tid % TX;
    const int ty  = tid / TX;
    const int blockRow = blockIdx.x * ROWS;

    for (int i = tid; i < DI * DO / 4; i += 256)
        reinterpret_cast<float4*>(Ws)[i] = reinterpret_cast<const float4*>(W)[i];

    for (int i = tid; i < ROWS * (DI / 4); i += 256) {
        int row = i / (DI / 4);
        int c4  = i % (DI / 4);
        int gr  = blockRow + row;
        float4 v = make_float4(0.f, 0.f, 0.f, 0.f);
        if (gr < N_NODES)
            v = reinterpret_cast<const float4*>(g_agg + gr * DI)[c4];
        xsT[(c4 * 4 + 0) * XS + row] = v.x;
        xsT[(c4 * 4 + 1) * XS + row] = v.y;
        xsT[(c4 * 4 + 2) * XS + row] = v.z;
        xsT[(c4 * 4 + 3) * XS + row] = v.w;
    }
    __syncthreads();

    float acc[4][4];
#pragma unroll
    for (int i = 0; i < 4; i++)
#pragma unroll
        for (int j = 0; j < 4; j++) acc[i][j] = 0.0f;

#pragma unroll
    for (int k = 0; k < DI; k++) {
        float4 a = *reinterpret_cast<const float4*>(&xsT[k * XS + ty * 4]);
        float4 b = *reinterpret_cast<const float4*>(&Ws [k * DO + tx * 4]);
        acc[0][0] += a.x * b.x; acc[0][1] += a.x * b.y; acc[0][2] += a.x * b.z; acc[0][3] += a.x * b.w;
        acc[1][0] += a.y * b.x; acc[1][1] += a.y * b.y; acc[1][2] += a.y * b.z; acc[1][3] += a.y * b.w;
        acc[2][0] += a.z * b.x; acc[2][1] += a.z * b.y; acc[2][2] += a.z * b.z; acc[2][3] += a.z * b.w;
        acc[3][0] += a.w * b.x; acc[3][1] += a.w * b.y; acc[3][2] += a.w * b.z; acc[3][3] += a.w * b.w;
    }

#pragma unroll
    for (int i = 0; i < 4; i++) {
        int row = blockRow + ty * 4 + i;
        if (row >= N_NODES) break;
        float dv = rsqrtf(g_deg[row]);
        float4 v = make_float4(dv * acc[i][0], dv * acc[i][1],
                               dv * acc[i][2], dv * acc[i][3]);
        *reinterpret_cast<float4*>(&g_h[row * DO + tx * 4]) = v;
        *reinterpret_cast<float4*>(&OUT[row * DO + tx * 4]) = v;   // self-loop init
    }
}

// ---------------- edge scatter: AGG[dst] += w * H[src]; 2 edges/thread-group ----
template <int D, int LAYER>
__global__ void k_scatter(const int* __restrict__ src,
                          const int* __restrict__ dst,
                          const float* __restrict__ w,
                          float* __restrict__ aggParam) {
    constexpr int TPE  = D / 4;
    constexpr int HALF = N_EDGES / 2;
    int tid = blockIdx.x * blockDim.x + threadIdx.x;
    int e = tid / TPE;
    int p = tid % TPE;
    if (e >= HALF) return;

    float* AGG = (LAYER == 1) ? g_agg : aggParam;
    const float* H = g_h;

    int eB = e + HALF;
    int   sA = __ldg(&src[e]),  dA = __ldg(&dst[e]);  float wA = __ldg(&w[e]);
    int   sB = __ldg(&src[eB]), dB = __ldg(&dst[eB]); float wB = __ldg(&w[eB]);

    float4 hA = *reinterpret_cast<const float4*>(H + sA * D + p * 4);
    float4 hB = *reinterpret_cast<const float4*>(H + sB * D + p * 4);
    red_add_v4(AGG + dA * D + p * 4, make_float4(wA*hA.x, wA*hA.y, wA*hA.z, wA*hA.w));
    red_add_v4(AGG + dB * D + p * 4, make_float4(wB*hB.x, wB*hB.y, wB*hB.z, wB*hB.w));
}

// ---------------- finalize: A = relu(rsqrt(deg)*A + b) ----------------
template <int D, int LAYER>
__global__ void k_final(float* __restrict__ aggParam, const float* __restrict__ b) {
    int i = blockIdx.x * blockDim.x + threadIdx.x;
    if (i >= N_NODES * D) return;
    float* A = (LAYER == 1) ? g_agg : aggParam;
    int row = i / D, col = i % D;
    float v = rsqrtf(g_deg[row]) * A[i] + b[col];
    A[i] = fmaxf(v, 0.0f);
}

extern "C" void kernel_launch(void* const* d_in, const int* in_sizes, int n_in,
                              void* d_out, int out_size) {
    const float* x   = (const float*)d_in[0];
    const int*   ei  = (const int*)  d_in[1];   // [2, E]
    const float* ew  = (const float*)d_in[2];
    const float* W1  = (const float*)d_in[3];
    const float* b1  = (const float*)d_in[4];
    const float* W2  = (const float*)d_in[5];
    const float* b2  = (const float*)d_in[6];
    float*       out = (float*)d_out;

    const int* src = ei;
    const int* dst = ei + N_EDGES;

    k_deg_init <<<(N_NODES + 255) / 256, 256>>>();
    k_deg_count<<<(N_EDGES / 4 + 255) / 256, 256>>>(dst, ew);

    // ---- layer 1 ----
    k_gemm64<1><<<(N_NODES + 63) / 64, 128>>>(x, W1);
    {
        int nthr = (N_EDGES / 2) * (D_HID / 4);
        k_scatter<D_HID, 1><<<(nthr + 255) / 256, 256>>>(src, dst, ew, nullptr);
    }
    k_final<D_HID, 1><<<(N_NODES * D_HID + 255) / 256, 256>>>(nullptr, b1);

    // ---- layer 2 ----
    k_gemm32<<<(N_NODES + 127) / 128, 256>>>(W2, out);
    {
        int nthr = (N_EDGES / 2) * (D_OUTF / 4);
        k_scatter<D_OUTF, 2><<<(nthr + 255) / 256, 256>>>(src, dst, ew, out);
    }
    k_final<D_OUTF, 2><<<(N_NODES * D_OUTF + 255) / 256, 256>>>(out, b2);
}